// round 17
// baseline (speedup 1.0000x reference)
#include <cuda_runtime.h>
#include <cuda_bf16.h>

// GraphGather / segment_sum:
//   out[b, :] = sum of feats[a, :] for membership[a] == b
// feats: [524288, 128] f32, membership: [524288] i32 (SORTED), out: [16384, 128] f32.
//
// R17: single-full-wave grid-stride version of the converged streamer.
//  - grid = 592 blocks = 4 x 148 SMs exactly, TPB=256 -> 32 warps/SM held
//    for the entire kernel: no wave transitions, no draining tail.
//  - each warp processes 32-row units u = gwarp + k*4736 (3-4 units); the
//    +1-unit warps sit in blocks 0..271, spread ~2/SM by placement.
//  - unit body = proven R16 path: one coalesced membership load, 4 batches
//    of 8 unconditional LDG.E.128 (MLP_p1=8, evict-first), boundary flushes
//    via red.global.add.v4.f32 (one 16B RMW per lane).
//  - output zeroed by the float4 prologue kernel (best measured prologue).

#define N_FEAT 128
#define FEAT4 (N_FEAT / 4)       // 32 float4 per row
#define TPB 256
#define N_SMS 148
#define GRID (4 * N_SMS)         // 592: exactly one full wave

__global__ __launch_bounds__(TPB)
void gg_zero4_kernel(float4* __restrict__ out, int n4) {
    int i = blockIdx.x * blockDim.x + threadIdx.x;
    if (i < n4) out[i] = make_float4(0.f, 0.f, 0.f, 0.f);
}

__device__ __forceinline__ void gg_flush(float* __restrict__ out,
                                         int seg, int lane, const float4& acc) {
    // byte offset = seg*512 + lane*16 -> 16B aligned.
    float* o = out + (size_t)seg * N_FEAT + lane * 4;
    asm volatile("red.global.add.v4.f32 [%0], {%1, %2, %3, %4};"
                 :: "l"(o), "f"(acc.x), "f"(acc.y), "f"(acc.z), "f"(acc.w)
                 : "memory");
}

__global__ __launch_bounds__(TPB)
void gg_segsum_kernel(const float4* __restrict__ feats,
                      const int* __restrict__ memb,
                      float* __restrict__ out,
                      int n_atoms) {
    const int gwarp = (blockIdx.x * TPB + threadIdx.x) >> 5;
    const int lane = threadIdx.x & 31;
    const int n_warps = GRID * (TPB / 32);            // 4736
    const int n_units = (n_atoms + 31) >> 5;          // 16384
    const unsigned FULL = 0xFFFFFFFFu;
    const int last = n_atoms - 1;

    for (int u = gwarp; u < n_units; u += n_warps) {
        const int row0 = u * 32;

        // One coalesced membership load for this unit's 32 rows.
        int mrow = row0 + lane;
        int mlane = memb[mrow <= last ? mrow : last];

        const int nrows = (row0 + 32 <= n_atoms) ? 32 : (n_atoms - row0);
        const float4* base = feats + (size_t)row0 * FEAT4 + lane;

        float4 acc = make_float4(0.f, 0.f, 0.f, 0.f);
        int cur = __shfl_sync(FULL, mlane, 0);

        if (nrows == 32) {
            #pragma unroll
            for (int bt = 0; bt < 4; ++bt) {
                // 8 independent 128-bit loads, back-to-back (MLP_p1 = 8).
                float4 v[8];
                #pragma unroll
                for (int i = 0; i < 8; ++i)
                    v[i] = __ldcs(base + (size_t)(bt * 8 + i) * FEAT4);

                #pragma unroll
                for (int i = 0; i < 8; ++i) {
                    int m = __shfl_sync(FULL, mlane, bt * 8 + i);
                    if (m != cur) {        // rare: ~1 boundary / unit
                        gg_flush(out, cur, lane, acc);
                        acc = make_float4(0.f, 0.f, 0.f, 0.f);
                        cur = m;
                    }
                    acc.x += v[i].x; acc.y += v[i].y;
                    acc.z += v[i].z; acc.w += v[i].w;
                }
            }
        } else {
            for (int i = 0; i < nrows; ++i) {
                float4 v = __ldcs(base + (size_t)i * FEAT4);
                int m = __shfl_sync(FULL, mlane, i);
                if (m != cur) {
                    gg_flush(out, cur, lane, acc);
                    acc = make_float4(0.f, 0.f, 0.f, 0.f);
                    cur = m;
                }
                acc.x += v.x; acc.y += v.y; acc.z += v.z; acc.w += v.w;
            }
        }

        gg_flush(out, cur, lane, acc);
    }
}

extern "C" void kernel_launch(void* const* d_in, const int* in_sizes, int n_in,
                              void* d_out, int out_size) {
    const float* feats = (const float*)d_in[0];
    const int* memb = (const int*)d_in[1];
    float* out = (float*)d_out;

    const int n_atoms = in_sizes[1];      // 524288
    const int n4 = out_size / 4;          // 524288 float4

    gg_zero4_kernel<<<(n4 + 255) / 256, 256>>>((float4*)out, n4);

    gg_segsum_kernel<<<GRID, TPB>>>((const float4*)feats, memb, out, n_atoms);
}